// round 1
// baseline (speedup 1.0000x reference)
#include <cuda_runtime.h>
#include <math.h>

#define B_ 4
#define S_ 2048
#define D_ 768
#define H_ 12
#define DH_ 64
#define NS_ (B_ * S_)          // 8192 rows into the projections

// Scratch: Q/K/V in [B,H,S,DH] layout (head-major so attention reads are dense)
__device__ float g_q[B_ * H_ * S_ * DH_];
__device__ float g_k[B_ * H_ * S_ * DH_];
__device__ float g_v[B_ * H_ * S_ * DH_];

// ---------------------------------------------------------------------------
// QKV projection: out[n, o] = (sum_k X[n,k] * W[o,k] + bias[o]) * scale
// stored into g_{q,k,v} as [b, h, s, dh] with h = o/64, dh = o%64.
// Block tile 64(n) x 64(o), K-chunk 32, 256 threads, 4x4 micro-tile.
// ---------------------------------------------------------------------------
__global__ __launch_bounds__(256) void qkv_gemm_kernel(
    const float* __restrict__ X, const float* __restrict__ W,
    const float* __restrict__ bias, int which, float scale)
{
    __shared__ float Xs[64][33];
    __shared__ float Ws[64][33];

    float* out = (which == 0) ? g_q : (which == 1) ? g_k : g_v;

    const int o0 = blockIdx.x * 64;
    const int n0 = blockIdx.y * 64;
    const int tid = threadIdx.x;
    const int tx = tid & 15;
    const int ty = tid >> 4;
    const int lc = tid & 31;   // k within chunk
    const int lr = tid >> 5;   // row group 0..7

    float acc[4][4] = {};

    for (int k0 = 0; k0 < D_; k0 += 32) {
        #pragma unroll
        for (int i = 0; i < 8; i++) {
            const int r = lr + 8 * i;
            Xs[r][lc] = X[(size_t)(n0 + r) * D_ + k0 + lc];
            Ws[r][lc] = W[(size_t)(o0 + r) * D_ + k0 + lc];
        }
        __syncthreads();
        #pragma unroll
        for (int k = 0; k < 32; k++) {
            float a[4], b[4];
            #pragma unroll
            for (int i = 0; i < 4; i++) a[i] = Xs[ty * 4 + i][k];
            #pragma unroll
            for (int j = 0; j < 4; j++) b[j] = Ws[tx * 4 + j][k];
            #pragma unroll
            for (int i = 0; i < 4; i++)
                #pragma unroll
                for (int j = 0; j < 4; j++)
                    acc[i][j] = fmaf(a[i], b[j], acc[i][j]);
        }
        __syncthreads();
    }

    const int h = o0 / DH_;  // o-tile (64 wide, 64-aligned) lies in one head
    #pragma unroll
    for (int i = 0; i < 4; i++) {
        const int n = n0 + ty * 4 + i;
        const int b = n / S_;
        const int s = n % S_;
        float4 v;
        float* vp = &v.x;
        #pragma unroll
        for (int j = 0; j < 4; j++) {
            const int o = o0 + tx * 4 + j;
            vp[j] = (acc[i][j] + bias[o]) * scale;
        }
        *(float4*)&out[(((size_t)b * H_ + h) * S_ + s) * DH_ + tx * 4] = v;
    }
}

// ---------------------------------------------------------------------------
// Flash-style attention: one block per (b, h, 64-row q tile).
// Online softmax, fp32 accumulators, 4x4 micro-tiles, 256 threads.
// Dynamic smem: Qs/Ks/Vs/Ps, each 64 x 65 floats (pad to dodge bank conflicts).
// ---------------------------------------------------------------------------
#define STRD 65
#define TILE_FLOATS (64 * STRD)

__global__ __launch_bounds__(256) void attn_kernel(float* __restrict__ out)
{
    extern __shared__ float sm[];
    float* Qs = sm;
    float* Ks = sm + TILE_FLOATS;
    float* Vs = sm + 2 * TILE_FLOATS;
    float* Ps = sm + 3 * TILE_FLOATS;

    const int qt = blockIdx.x;   // 0..31
    const int h  = blockIdx.y;   // 0..11
    const int b  = blockIdx.z;   // 0..3
    const int tid = threadIdx.x;
    const int tx = tid & 15;
    const int ty = tid >> 4;

    const size_t base = ((size_t)b * H_ + h) * S_ * DH_;

    // Load Q tile (scale already folded in by the projection kernel)
    for (int i = tid; i < 64 * 64; i += 256) {
        const int r = i >> 6, c = i & 63;
        Qs[r * STRD + c] = g_q[base + (size_t)(qt * 64 + r) * DH_ + c];
    }

    float o[4][4] = {};
    float m[4], l[4];
    #pragma unroll
    for (int i = 0; i < 4; i++) { m[i] = -INFINITY; l[i] = 0.f; }

    for (int kt = 0; kt < S_ / 64; kt++) {
        __syncthreads();  // prior iteration done reading Ks/Vs/Ps
        for (int i = tid; i < 64 * 64; i += 256) {
            const int r = i >> 6, c = i & 63;
            const size_t g = base + (size_t)(kt * 64 + r) * DH_ + c;
            Ks[r * STRD + c] = g_k[g];
            Vs[r * STRD + c] = g_v[g];
        }
        __syncthreads();

        // scores s[i][j] = Q[qrow] . K[krow]   (scale folded into Q)
        float s[4][4] = {};
        #pragma unroll
        for (int k = 0; k < 64; k++) {
            float a[4], bb[4];
            #pragma unroll
            for (int i = 0; i < 4; i++) a[i]  = Qs[(ty * 4 + i) * STRD + k];
            #pragma unroll
            for (int j = 0; j < 4; j++) bb[j] = Ks[(tx * 4 + j) * STRD + k];
            #pragma unroll
            for (int i = 0; i < 4; i++)
                #pragma unroll
                for (int j = 0; j < 4; j++)
                    s[i][j] = fmaf(a[i], bb[j], s[i][j]);
        }

        // online softmax update per q-row (rows owned by the 16-lane ty group)
        #pragma unroll
        for (int i = 0; i < 4; i++) {
            float mt = fmaxf(fmaxf(s[i][0], s[i][1]), fmaxf(s[i][2], s[i][3]));
            #pragma unroll
            for (int off = 8; off >= 1; off >>= 1)
                mt = fmaxf(mt, __shfl_xor_sync(0xffffffffu, mt, off));
            const float m_new = fmaxf(m[i], mt);
            const float alpha = __expf(m[i] - m_new);
            float rs = 0.f;
            #pragma unroll
            for (int j = 0; j < 4; j++) {
                s[i][j] = __expf(s[i][j] - m_new);
                rs += s[i][j];
            }
            #pragma unroll
            for (int off = 8; off >= 1; off >>= 1)
                rs += __shfl_xor_sync(0xffffffffu, rs, off);
            l[i] = l[i] * alpha + rs;
            m[i] = m_new;
            #pragma unroll
            for (int j = 0; j < 4; j++) o[i][j] *= alpha;
        }

        // publish P tile
        #pragma unroll
        for (int i = 0; i < 4; i++)
            #pragma unroll
            for (int j = 0; j < 4; j++)
                Ps[(ty * 4 + i) * STRD + tx * 4 + j] = s[i][j];
        __syncthreads();

        // O += P @ V
        #pragma unroll
        for (int k = 0; k < 64; k++) {
            float p[4], vv[4];
            #pragma unroll
            for (int i = 0; i < 4; i++) p[i]  = Ps[(ty * 4 + i) * STRD + k];
            #pragma unroll
            for (int j = 0; j < 4; j++) vv[j] = Vs[k * STRD + tx * 4 + j];
            #pragma unroll
            for (int i = 0; i < 4; i++)
                #pragma unroll
                for (int j = 0; j < 4; j++)
                    o[i][j] = fmaf(p[i], vv[j], o[i][j]);
        }
    }

    // normalize + write out[b, s, h*64 + dh]
    #pragma unroll
    for (int i = 0; i < 4; i++) {
        const int sq = qt * 64 + ty * 4 + i;
        const float inv = 1.0f / l[i];
        float4 v;
        v.x = o[i][0] * inv; v.y = o[i][1] * inv;
        v.z = o[i][2] * inv; v.w = o[i][3] * inv;
        *(float4*)&out[((size_t)b * S_ + sq) * D_ + h * DH_ + tx * 4] = v;
    }
}

// ---------------------------------------------------------------------------
extern "C" void kernel_launch(void* const* d_in, const int* in_sizes, int n_in,
                              void* d_out, int out_size)
{
    (void)in_sizes; (void)n_in; (void)out_size;
    const float* x  = (const float*)d_in[0];
    const float* Wq = (const float*)d_in[1];
    const float* bq = (const float*)d_in[2];
    const float* Wk = (const float*)d_in[3];
    const float* bk = (const float*)d_in[4];
    const float* Wv = (const float*)d_in[5];
    const float* bv = (const float*)d_in[6];
    float* out = (float*)d_out;

    const float qscale = 1.0f / 8.0f;  // 1/sqrt(DH), folded into Q

    dim3 ggrid(D_ / 64, NS_ / 64);     // (12, 128)
    qkv_gemm_kernel<<<ggrid, 256>>>(x, Wq, bq, 0, qscale);
    qkv_gemm_kernel<<<ggrid, 256>>>(x, Wk, bk, 1, 1.0f);
    qkv_gemm_kernel<<<ggrid, 256>>>(x, Wv, bv, 2, 1.0f);

    const int smem_bytes = 4 * TILE_FLOATS * (int)sizeof(float);  // ~65 KB
    cudaFuncSetAttribute(attn_kernel,
                         cudaFuncAttributeMaxDynamicSharedMemorySize, smem_bytes);
    dim3 agrid(S_ / 64, H_, B_);       // (32, 12, 4)
    attn_kernel<<<agrid, 256, smem_bytes>>>(out);
}